// round 6
// baseline (speedup 1.0000x reference)
#include <cuda_runtime.h>
#include <cstdint>

// Problem constants
#define NN    8192
#define NP1   8193
#define AB    16384ULL                    // A_low base (floats)
#define MM    67125249ULL                 // NP1*NP1
#define AUB   (AB + MM)                   // A_up base = 67141633
#define LR0   134258689ULL                // A_up last-row start (floats)
#define T_TOT 134266882ULL                // total output floats

// Split point: byte 503513088 (float 125878272). mod 16 == 0.
// Region 1 = [0, F2): head, all A_low diag (max pos 67141632), A_up diag k<=7168.
// Region 2 = [F2, end): A_up diag k in [7169, 8191], last row (+corner).
#define F2_FLOATS 125878272ULL
#define BYTES1    503513088ULL
#define KSPLIT    7169                    // first A_up-diag k in region 2

// patch1 segments: [0,16384) head | [16384,24577) A_low diag k=0..8192 |
//                  [24577,31746) A_up diag k=0..7168
#define P1_HEAD 16384
#define P1_DLOW (P1_HEAD + NP1)           // 24577
#define P1_TOT  (P1_DLOW + KSPLIT)        // 31746

// patch2 segments: [0,8193) last row col 0..8192 | [8193,9216) A_up diag k=7169..8191
#define P2_LROW NP1
#define P2_TOT  (P2_LROW + (NN - KSPLIT)) // 9216

#define THREADS 512

__global__ void __launch_bounds__(THREADS) relu_patch_low(
        const float* __restrict__ lower,
        const float* __restrict__ upper,
        const float* __restrict__ alphas,
        float* __restrict__ out) {
    const int w = blockIdx.x * THREADS + threadIdx.x;
    if (w >= P1_TOT) return;

    if (w < P1_HEAD) {
        // conc_low / conc_up (coalesced)
        const int i = w & (NN - 1);
        const float l = lower[i];
        const float u = upper[i];
        float val;
        if (w < NN) {
            const float a = fminf(fmaxf(alphas[i], 0.f), 1.f);
            const bool active   = (u > 0.f) && (l >= 0.f);
            const bool unstable = (u > 0.f) && (l < 0.f);
            val = active ? l : (unstable ? a * l : 0.f);
        } else {
            val = (u > 0.f) ? u : 0.f;
        }
        out[w] = val;
        return;
    }

    size_t pos;
    float  val;
    if (w < P1_DLOW) {
        // A_low diagonal, k = 0..8192
        const int k = w - P1_HEAD;
        if (k == NN) {
            val = 1.f;
        } else {
            const float l = lower[k];
            const float u = upper[k];
            const bool active   = (u > 0.f) && (l >= 0.f);
            const bool unstable = (u > 0.f) && (l < 0.f);
            const float a = fminf(fmaxf(alphas[k], 0.f), 1.f);
            val = active ? 1.f : (unstable ? a : 0.f);
        }
        pos = AB + (size_t)k * (size_t)(NP1 + 1);
    } else {
        // A_up diagonal, k = 0..KSPLIT-1
        const int k = w - P1_DLOW;
        const float l = lower[k];
        const float u = upper[k];
        const bool active   = (u > 0.f) && (l >= 0.f);
        const bool unstable = (u > 0.f) && (l < 0.f);
        const float d = u - l;
        const float lam = u / ((d == 0.f) ? 1.f : d);
        val = active ? 1.f : (unstable ? lam : 0.f);
        pos = AUB + (size_t)k * (size_t)(NP1 + 1);
    }
    __stcs(out + pos, val);   // scattered streaming store
}

__global__ void __launch_bounds__(THREADS) relu_patch_high(
        const float* __restrict__ lower,
        const float* __restrict__ upper,
        float* __restrict__ out) {
    const int w = blockIdx.x * THREADS + threadIdx.x;
    if (w >= P2_TOT) return;

    if (w < P2_LROW) {
        // A_up last row (coalesced), col NN -> 1.0
        const int col = w;
        float val;
        if (col == NN) {
            val = 1.f;
        } else {
            const float l = lower[col];
            const float u = upper[col];
            const bool unstable = (u > 0.f) && (l < 0.f);
            const float d = u - l;
            const float lam = u / ((d == 0.f) ? 1.f : d);
            val = unstable ? (-lam * l) : 0.f;
        }
        out[LR0 + (size_t)col] = val;
        return;
    }

    // A_up diagonal, k = KSPLIT..NN-1
    const int k = KSPLIT + (w - P2_LROW);
    const float l = lower[k];
    const float u = upper[k];
    const bool active   = (u > 0.f) && (l >= 0.f);
    const bool unstable = (u > 0.f) && (l < 0.f);
    const float d = u - l;
    const float lam = u / ((d == 0.f) ? 1.f : d);
    const float val = active ? 1.f : (unstable ? lam : 0.f);
    __stcs(out + AUB + (size_t)k * (size_t)(NP1 + 1), val);
}

// Streams/events created once at program load (no device-memory allocation;
// kernel_launch itself issues identical work on every call).
namespace {
struct ForkCtx {
    cudaStream_t sP;
    cudaEvent_t  eM1, eP1;
    ForkCtx() {
        cudaStreamCreateWithFlags(&sP, cudaStreamNonBlocking);
        cudaEventCreateWithFlags(&eM1, cudaEventDisableTiming);
        cudaEventCreateWithFlags(&eP1, cudaEventDisableTiming);
    }
};
ForkCtx g_fork;
}

extern "C" void kernel_launch(void* const* d_in, const int* in_sizes, int n_in,
                              void* d_out, int out_size) {
    const float* lower  = (const float*)d_in[0];
    const float* upper  = (const float*)d_in[1];
    const float* alphas = (const float*)d_in[2];
    float* out = (float*)d_out;

    // memset1: [0, BYTES1) — base-aligned, size % 16 == 0 (fast path).
    cudaMemsetAsync(d_out, 0, BYTES1, 0);

    // Fork: patch of region 1 runs concurrently with memset2.
    cudaEventRecord(g_fork.eM1, 0);
    cudaStreamWaitEvent(g_fork.sP, g_fork.eM1, 0);
    relu_patch_low<<<(P1_TOT + THREADS - 1) / THREADS, THREADS, 0, g_fork.sP>>>(
        lower, upper, alphas, out);
    cudaEventRecord(g_fork.eP1, g_fork.sP);

    // memset2: top region [BYTES1, end). size % 16 == 8 (same class as the
    // known-fast full-buffer memset from R1).
    cudaMemsetAsync((char*)d_out + BYTES1, 0,
                    (size_t)out_size * 4 - BYTES1, 0);

    // patch2: small serialized tail on stream 0.
    relu_patch_high<<<(P2_TOT + THREADS - 1) / THREADS, THREADS>>>(
        lower, upper, out);

    // Join the forked stream back before capture ends.
    cudaStreamWaitEvent(0, g_fork.eP1, 0);
}

// round 7
// speedup vs baseline: 1.5117x; 1.5117x over previous
#include <cuda_runtime.h>
#include <cstdint>

// Problem constants
#define NN    8192
#define NP1   8193
#define AB    16384ULL                    // A_low base (floats)
#define MM    67125249ULL                 // NP1*NP1
#define AUB   (AB + MM)                   // A_up base
#define LR0   134258689ULL                // A_up last-row start (floats); NOT 16B-aligned

// Flat work decomposition (512-thread blocks, one wave):
//   [0, 4096)       : head float4 stores  (conc_low|conc_up, 16384 floats)
//   [4096, 12289)   : A_up last row scalar, col 0..8192 (col 8192 -> 1.0)
//   [12289, 20482)  : A_low diagonal, k = 0..8192 (k = 8192 -> 1.0)
//   [20482, 28674)  : A_up diagonal,  k = 0..8191
#define W_HEAD4  4096
#define W_LROW   (W_HEAD4 + NP1)          // 12289
#define W_DLOW   (W_LROW + NP1)           // 20482
#define W_TOT    (W_DLOW + NN)            // 28674

#define THREADS 512

__global__ void __launch_bounds__(THREADS) relu_relax_patch(
        const float* __restrict__ lower,
        const float* __restrict__ upper,
        const float* __restrict__ alphas,
        float* __restrict__ out) {
    const int w = blockIdx.x * THREADS + threadIdx.x;
    if (w >= W_TOT) return;

    if (w < W_HEAD4) {
        // conc_low / conc_up, 4 floats per thread (16B-aligned vector store).
        // Threads [0,2048) -> conc_low, [2048,4096) -> conc_up.
        const int i0 = (w << 2) & (NN - 1);
        const float4 l4 = *reinterpret_cast<const float4*>(lower + i0);
        const float4 u4 = *reinterpret_cast<const float4*>(upper + i0);
        float4 v;
        if (w < W_HEAD4 / 2) {
            const float4 a4 = *reinterpret_cast<const float4*>(alphas + i0);
            #define CL(lx, ux, ax) \
                (((ux) > 0.f && (lx) >= 0.f) ? (lx) : \
                 (((ux) > 0.f && (lx) < 0.f) ? fminf(fmaxf((ax),0.f),1.f) * (lx) : 0.f))
            v.x = CL(l4.x, u4.x, a4.x);
            v.y = CL(l4.y, u4.y, a4.y);
            v.z = CL(l4.z, u4.z, a4.z);
            v.w = CL(l4.w, u4.w, a4.w);
            #undef CL
        } else {
            v.x = (u4.x > 0.f) ? u4.x : 0.f;
            v.y = (u4.y > 0.f) ? u4.y : 0.f;
            v.z = (u4.z > 0.f) ? u4.z : 0.f;
            v.w = (u4.w > 0.f) ? u4.w : 0.f;
        }
        reinterpret_cast<float4*>(out)[w] = v;
        return;
    }

    if (w < W_LROW) {
        // A_up last row (scalar; LR0 not 16B-aligned), col NN -> 1.0
        const int col = w - W_HEAD4;
        float val;
        if (col == NN) {
            val = 1.f;
        } else {
            const float l = lower[col];
            const float u = upper[col];
            const bool unstable = (u > 0.f) && (l < 0.f);
            const float d = u - l;
            const float lam = __fdividef(u, (d == 0.f) ? 1.f : d);
            val = unstable ? (-lam * l) : 0.f;
        }
        out[LR0 + (size_t)col] = val;
        return;
    }

    size_t pos;
    float  val;
    if (w < W_DLOW) {
        // A_low diagonal (scattered, stride 8194 floats)
        const int k = w - W_LROW;
        if (k == NN) {
            val = 1.f;
        } else {
            const float l = lower[k];
            const float u = upper[k];
            const bool active   = (u > 0.f) && (l >= 0.f);
            const bool unstable = (u > 0.f) && (l < 0.f);
            const float a = fminf(fmaxf(alphas[k], 0.f), 1.f);
            val = active ? 1.f : (unstable ? a : 0.f);
        }
        pos = AB + (size_t)k * (size_t)(NP1 + 1);
    } else {
        // A_up diagonal, k = 0..NN-1 (k = NN handled in last-row segment)
        const int k = w - W_DLOW;
        const float l = lower[k];
        const float u = upper[k];
        const bool active   = (u > 0.f) && (l >= 0.f);
        const bool unstable = (u > 0.f) && (l < 0.f);
        const float d = u - l;
        const float lam = __fdividef(u, (d == 0.f) ? 1.f : d);
        val = active ? 1.f : (unstable ? lam : 0.f);
        pos = AUB + (size_t)k * (size_t)(NP1 + 1);
    }
    // Scattered diagonal store: L2-resident, no L1 allocation
    __stcg(out + pos, val);
}

extern "C" void kernel_launch(void* const* d_in, const int* in_sizes, int n_in,
                              void* d_out, int out_size) {
    const float* lower  = (const float*)d_in[0];
    const float* upper  = (const float*)d_in[1];
    const float* alphas = (const float*)d_in[2];
    float* out = (float*)d_out;

    // Full-buffer, base-address memset: the ONLY configuration that takes the
    // driver's fast (~7.4 TB/s) path. Do not offset, shrink, or split it
    // (R4/R6 both measured ~4.8 TB/s for any other shape).
    cudaMemsetAsync(d_out, 0, (size_t)out_size * sizeof(float), 0);

    const int blocks = (W_TOT + THREADS - 1) / THREADS;   // 57
    relu_relax_patch<<<blocks, THREADS>>>(lower, upper, alphas, out);
}